// round 6
// baseline (speedup 1.0000x reference)
#include <cuda_runtime.h>
#include <cuda_bf16.h>

// ForwardKinematics: B=524288, NA=7 joints, NJ=8 transforms.
// out[n] = M0*...*M6*F7, Mi = Fi*[[R(theta_i,a_i),0],[0,1]]
// rot(Mi) = A_i + sin*(A_i K_i) + (1-cos)*(A_i(aa^T) - A_i); trans(Mi)=t_i.
//
// R6: kernel is L1-wavefront bound; biggest term = scalar LDS.64 broadcast
// constant reads (~220 wf/warp). Repack splatted constants into contiguous
// per-joint A/B/C/t arrays and read them as ulonglong2 (LDS.128 broadcast =
// 1 wavefront per 2 constants). f32x2 packed math as R5 (2 elems/thread:
// g and g+n/2).

#define NACT 7
#define THREADS 256

typedef unsigned long long u64;

__device__ __forceinline__ u64 fma2(u64 a, u64 b, u64 c) {
    u64 d; asm("fma.rn.f32x2 %0, %1, %2, %3;" : "=l"(d) : "l"(a), "l"(b), "l"(c)); return d;
}
__device__ __forceinline__ u64 mul2(u64 a, u64 b) {
    u64 d; asm("mul.rn.f32x2 %0, %1, %2;" : "=l"(d) : "l"(a), "l"(b)); return d;
}
__device__ __forceinline__ u64 pack2(float lo, float hi) {
    u64 d; asm("mov.b64 %0, {%1, %2};" : "=l"(d) : "f"(lo), "f"(hi)); return d;
}
__device__ __forceinline__ float2 unpack2(u64 v) {
    float lo, hi; asm("mov.b64 {%0, %1}, %2;" : "=f"(lo), "=f"(hi) : "l"(v));
    return make_float2(lo, hi);
}

__global__ __launch_bounds__(THREADS)
void fk_kernel(const float* __restrict__ jp,    // (B,7)
               const float* __restrict__ ft,    // (8,4,4)
               const float* __restrict__ axes,  // (7,3)
               float* __restrict__ out,         // (B,4,4)
               int n)
{
    // splatted constants, contiguous per coefficient family for LDS.128 reads
    __shared__ alignas(16) float2 sA[NACT][10];  // A[9] + pad
    __shared__ alignas(16) float2 sB[NACT][10];  // (A@K)[9] + pad
    __shared__ alignas(16) float2 sC[NACT][10];  // (A@(aa^T)-A)[9] + pad
    __shared__ alignas(16) float2 sT[NACT][4];   // t[3] + pad
    __shared__ alignas(16) float2 sF7v[12];      // F7 top 3x4

    const int tid = threadIdx.x;

    if (tid < NACT) {
        const float* F = ft + tid * 16;
        float A[9];
        #pragma unroll
        for (int r = 0; r < 3; r++)
            #pragma unroll
            for (int c = 0; c < 3; c++)
                A[r * 3 + c] = F[r * 4 + c];
        const float ax = axes[tid * 3 + 0];
        const float ay = axes[tid * 3 + 1];
        const float az = axes[tid * 3 + 2];
        #pragma unroll
        for (int k = 0; k < 9; k++) sA[tid][k] = make_float2(A[k], A[k]);
        sA[tid][9] = make_float2(0.f, 0.f);
        #pragma unroll
        for (int r = 0; r < 3; r++) {
            float b0 = A[r * 3 + 1] * az - A[r * 3 + 2] * ay;
            float b1 = A[r * 3 + 2] * ax - A[r * 3 + 0] * az;
            float b2 = A[r * 3 + 0] * ay - A[r * 3 + 1] * ax;
            sB[tid][r * 3 + 0] = make_float2(b0, b0);
            sB[tid][r * 3 + 1] = make_float2(b1, b1);
            sB[tid][r * 3 + 2] = make_float2(b2, b2);
        }
        sB[tid][9] = make_float2(0.f, 0.f);
        #pragma unroll
        for (int r = 0; r < 3; r++) {
            float dp = A[r * 3 + 0] * ax + A[r * 3 + 1] * ay + A[r * 3 + 2] * az;
            float c0 = dp * ax - A[r * 3 + 0];
            float c1 = dp * ay - A[r * 3 + 1];
            float c2 = dp * az - A[r * 3 + 2];
            sC[tid][r * 3 + 0] = make_float2(c0, c0);
            sC[tid][r * 3 + 1] = make_float2(c1, c1);
            sC[tid][r * 3 + 2] = make_float2(c2, c2);
        }
        sC[tid][9] = make_float2(0.f, 0.f);
        sT[tid][0] = make_float2(F[3],  F[3]);
        sT[tid][1] = make_float2(F[7],  F[7]);
        sT[tid][2] = make_float2(F[11], F[11]);
        sT[tid][3] = make_float2(0.f, 0.f);
    }
    if (tid < 12) {
        float v = ft[7 * 16 + tid];
        sF7v[tid] = make_float2(v, v);
    }
    __syncthreads();

    const int half = n >> 1;   // B = 524288, even
    const int g = blockIdx.x * THREADS + tid;
    if (g >= half) return;

    const float* p0 = jp + (size_t)g * NACT;
    const float* p1 = jp + (size_t)(g + half) * NACT;
    float th0[NACT], th1[NACT];
    #pragma unroll
    for (int i = 0; i < NACT; i++) th0[i] = p0[i];
    #pragma unroll
    for (int i = 0; i < NACT; i++) th1[i] = p1[i];

    u64 Tr[9], Tt[3];

    // joint 0: T = M0
    {
        float s0, c0, s1, c1;
        __sincosf(th0[0], &s0, &c0);
        __sincosf(th1[0], &s1, &c1);
        u64 s2 = pack2(s0, s1);
        u64 o2 = pack2(1.0f - c0, 1.0f - c1);
        const ulonglong2* Av = reinterpret_cast<const ulonglong2*>(sA[0]);
        const ulonglong2* Bv = reinterpret_cast<const ulonglong2*>(sB[0]);
        const ulonglong2* Cv = reinterpret_cast<const ulonglong2*>(sC[0]);
        #pragma unroll
        for (int kp = 0; kp < 4; kp++) {
            ulonglong2 a = Av[kp], b = Bv[kp], c = Cv[kp];
            Tr[2 * kp + 0] = fma2(o2, c.x, fma2(s2, b.x, a.x));
            Tr[2 * kp + 1] = fma2(o2, c.y, fma2(s2, b.y, a.y));
        }
        {
            ulonglong2 a = Av[4], b = Bv[4], c = Cv[4];
            Tr[8] = fma2(o2, c.x, fma2(s2, b.x, a.x));
        }
        const ulonglong2* Tv = reinterpret_cast<const ulonglong2*>(sT[0]);
        ulonglong2 t01 = Tv[0], t23 = Tv[1];
        Tt[0] = t01.x; Tt[1] = t01.y; Tt[2] = t23.x;
    }

    // joints 1..6: T = T @ Mi
    #pragma unroll
    for (int i = 1; i < NACT; i++) {
        float s0, c0, s1, c1;
        __sincosf(th0[i], &s0, &c0);
        __sincosf(th1[i], &s1, &c1);
        u64 s2 = pack2(s0, s1);
        u64 o2 = pack2(1.0f - c0, 1.0f - c1);

        const ulonglong2* Av = reinterpret_cast<const ulonglong2*>(sA[i]);
        const ulonglong2* Bv = reinterpret_cast<const ulonglong2*>(sB[i]);
        const ulonglong2* Cv = reinterpret_cast<const ulonglong2*>(sC[i]);

        u64 M[9];
        #pragma unroll
        for (int kp = 0; kp < 4; kp++) {
            ulonglong2 a = Av[kp], b = Bv[kp], c = Cv[kp];
            M[2 * kp + 0] = fma2(o2, c.x, fma2(s2, b.x, a.x));
            M[2 * kp + 1] = fma2(o2, c.y, fma2(s2, b.y, a.y));
        }
        {
            ulonglong2 a = Av[4], b = Bv[4], c = Cv[4];
            M[8] = fma2(o2, c.x, fma2(s2, b.x, a.x));
        }

        u64 R[9];
        #pragma unroll
        for (int r = 0; r < 3; r++)
            #pragma unroll
            for (int c2i = 0; c2i < 3; c2i++)
                R[r * 3 + c2i] = fma2(Tr[r * 3 + 2], M[6 + c2i],
                                 fma2(Tr[r * 3 + 1], M[3 + c2i],
                                 mul2(Tr[r * 3 + 0], M[0 + c2i])));

        const ulonglong2* Tv = reinterpret_cast<const ulonglong2*>(sT[i]);
        ulonglong2 t01 = Tv[0], t23 = Tv[1];
        #pragma unroll
        for (int r = 0; r < 3; r++)
            Tt[r] = fma2(Tr[r * 3 + 2], t23.x,
                    fma2(Tr[r * 3 + 1], t01.y,
                    fma2(Tr[r * 3 + 0], t01.x, Tt[r])));

        #pragma unroll
        for (int k = 0; k < 9; k++) Tr[k] = R[k];
    }

    // final: T = T @ F7  (F7 rows sequential -> 6 LDS.128 broadcasts)
    u64 Rr[9], Ot[3];
    {
        const ulonglong2* Fv = reinterpret_cast<const ulonglong2*>(sF7v);
        ulonglong2 f0 = Fv[0], f1 = Fv[1];   // F7[0..3]
        ulonglong2 f2 = Fv[2], f3 = Fv[3];   // F7[4..7]
        ulonglong2 f4 = Fv[4], f5 = Fv[5];   // F7[8..11]
        u64 Frow[12] = { f0.x, f0.y, f1.x, f1.y,
                         f2.x, f2.y, f3.x, f3.y,
                         f4.x, f4.y, f5.x, f5.y };
        #pragma unroll
        for (int r = 0; r < 3; r++) {
            #pragma unroll
            for (int c2i = 0; c2i < 3; c2i++)
                Rr[r * 3 + c2i] = fma2(Tr[r * 3 + 2], Frow[8 + c2i],
                                  fma2(Tr[r * 3 + 1], Frow[4 + c2i],
                                  mul2(Tr[r * 3 + 0], Frow[0 + c2i])));
            Ot[r] = fma2(Tr[r * 3 + 2], Frow[11],
                    fma2(Tr[r * 3 + 1], Frow[7],
                    fma2(Tr[r * 3 + 0], Frow[3], Tt[r])));
        }
    }

    // unpack and store both elements
    float2 rr[9], ot[3];
    #pragma unroll
    for (int k = 0; k < 9; k++) rr[k] = unpack2(Rr[k]);
    #pragma unroll
    for (int k = 0; k < 3; k++) ot[k] = unpack2(Ot[k]);

    {
        float4* o0 = reinterpret_cast<float4*>(out + (size_t)g * 16);
        o0[0] = make_float4(rr[0].x, rr[1].x, rr[2].x, ot[0].x);
        o0[1] = make_float4(rr[3].x, rr[4].x, rr[5].x, ot[1].x);
        o0[2] = make_float4(rr[6].x, rr[7].x, rr[8].x, ot[2].x);
        o0[3] = make_float4(0.0f, 0.0f, 0.0f, 1.0f);

        float4* o1 = reinterpret_cast<float4*>(out + (size_t)(g + half) * 16);
        o1[0] = make_float4(rr[0].y, rr[1].y, rr[2].y, ot[0].y);
        o1[1] = make_float4(rr[3].y, rr[4].y, rr[5].y, ot[1].y);
        o1[2] = make_float4(rr[6].y, rr[7].y, rr[8].y, ot[2].y);
        o1[3] = make_float4(0.0f, 0.0f, 0.0f, 1.0f);
    }
}

extern "C" void kernel_launch(void* const* d_in, const int* in_sizes, int n_in,
                              void* d_out, int out_size) {
    const float* jp   = (const float*)d_in[0];  // joint_positions (B,7)
    const float* ft   = (const float*)d_in[1];  // fixed_transforms (8,4,4)
    const float* axes = (const float*)d_in[2];  // joint_axes (7,3)
    float* out = (float*)d_out;
    const int n = in_sizes[0] / NACT;
    const int half = n >> 1;                    // B is even
    const int blocks = (half + THREADS - 1) / THREADS;
    fk_kernel<<<blocks, THREADS>>>(jp, ft, axes, out, n);
}